// round 1
// baseline (speedup 1.0000x reference)
#include <cuda_runtime.h>

#define NBH   1536          // 128 batches * 12 heads
#define ROW   38809         // 197*197 elements per (b,h) slice
#define P     196           // 14*14 patch grid
#define HS    14
#define BIGL  0x3FFFFFFF

__device__ float g_partial[NBH];

__global__ __launch_bounds__(256) void blob_entropy_kernel(const float* __restrict__ in) {
    const int bh = blockIdx.x;
    const int t  = threadIdx.x;          // 0..255, only 0..195 own a pixel

    __shared__ int   lab[P];
    __shared__ float psum[P];
    __shared__ float red[256];
    __shared__ int   changed;

    // ---- load CLS->patch scores (196 contiguous floats) ----
    float x = 0.f;
    if (t < P) x = in[(size_t)bh * ROW + 1 + t];

    // ---- mean over 196 ----
    red[t] = (t < P) ? x : 0.f;
    __syncthreads();
    #pragma unroll
    for (int s = 128; s > 0; s >>= 1) {
        if (t < s) red[t] += red[t + s];
        __syncthreads();
    }
    const float m = red[0] / (float)P;
    __syncthreads();                      // red reused below

    const bool  fg = (t < P) && (x > m);
    const float v  = fg ? (x - m + 1e-9f) : 0.f;   // relu(x-m)+1e-9 on mask

    if (t < P) {
        lab[t]  = fg ? t : BIGL;
        psum[t] = 0.f;
    }
    __syncthreads();

    // ---- 8-connected CC: min-label propagation + pointer jumping ----
    const int r = t / HS, c = t % HS;
    for (int iter = 0; iter < P; ++iter) {
        if (t == 0) changed = 0;
        __syncthreads();                  // reset visible
        if (fg) {
            int l = lab[t];
            #pragma unroll
            for (int dr = -1; dr <= 1; ++dr) {
                #pragma unroll
                for (int dc = -1; dc <= 1; ++dc) {
                    const int rr = r + dr, cc = c + dc;
                    if (rr >= 0 && rr < HS && cc >= 0 && cc < HS) {
                        const int ln = lab[rr * HS + cc];
                        if (ln < l) l = ln;
                    }
                }
            }
            const int l2 = lab[l];        // pointer jump (l < P when fg)
            if (l2 < l) l = l2;
            if (l < lab[t]) { lab[t] = l; changed = 1; }
        }
        __syncthreads();                  // updates + flag visible
        const int ch = changed;
        __syncthreads();                  // protect next-iter reset from late readers
        if (!ch) break;
    }

    // ---- B = sum of xv over mask ----
    red[t] = v;
    __syncthreads();
    #pragma unroll
    for (int s = 128; s > 0; s >>= 1) {
        if (t < s) red[t] += red[t + s];
        __syncthreads();
    }
    const float B = red[0];
    __syncthreads();

    // ---- per-component sums ----
    if (fg) atomicAdd(&psum[lab[t]], v);
    __syncthreads();

    // ---- entropy of component roots ----
    float h = 0.f;
    if (fg && lab[t] == t) {
        const float p = psum[t] / B;      // in (0,1]
        h = -p * logf(p);
    }
    red[t] = h;
    __syncthreads();
    #pragma unroll
    for (int s = 128; s > 0; s >>= 1) {
        if (t < s) red[t] += red[t + s];
        __syncthreads();
    }
    if (t == 0) g_partial[bh] = red[0];
}

__global__ __launch_bounds__(256) void blob_reduce_kernel(float* __restrict__ out) {
    __shared__ float red[256];
    const int t = threadIdx.x;
    float s = 0.f;
    for (int i = t; i < NBH; i += 256) s += g_partial[i];
    red[t] = s;
    __syncthreads();
    #pragma unroll
    for (int st = 128; st > 0; st >>= 1) {
        if (t < st) red[t] += red[t + st];
        __syncthreads();
    }
    if (t == 0) out[0] = red[0] / (float)NBH;
}

extern "C" void kernel_launch(void* const* d_in, const int* in_sizes, int n_in,
                              void* d_out, int out_size) {
    const float* in  = (const float*)d_in[0];
    float*       out = (float*)d_out;
    blob_entropy_kernel<<<NBH, 256>>>(in);
    blob_reduce_kernel<<<1, 256>>>(out);
}

// round 2
// speedup vs baseline: 1.1217x; 1.1217x over previous
#include <cuda_runtime.h>

#define NBH   1536          // 128 batches * 12 heads
#define ROW   38809         // 197*197 elements per (b,h) slice
#define P     196           // 14*14 patch grid
#define HS    14
#define BIGL  0x3FFFFFFF

__device__ float        g_partial[NBH];
__device__ unsigned int g_count = 0;

__device__ __forceinline__ float warp_sum(float v) {
    #pragma unroll
    for (int o = 16; o > 0; o >>= 1) v += __shfl_down_sync(0xFFFFFFFFu, v, o);
    return v;
}

__global__ __launch_bounds__(256) void blob_kernel(const float* __restrict__ in,
                                                   float* __restrict__ out) {
    const int bh   = blockIdx.x;
    const int t    = threadIdx.x;           // 0..255
    const int warp = t >> 5, lane = t & 31;
    const bool own = t < P;
    const int r = t / HS, c = t % HS;
    const int idx = (r + 1) * 16 + (c + 1); // padded 16x16 index (valid when own)

    __shared__ int   lab[256];              // padded 16x16 label grid, border=BIGL
    __shared__ float psum[256];
    __shared__ float wred[8];
    __shared__ bool  amLast;

    // ---- load CLS->patch scores (196 contiguous floats) ----
    float x = own ? in[(size_t)bh * ROW + 1 + t] : 0.f;

    // ---- mean over 196 (warp shuffles, 2 barriers) ----
    float s = warp_sum(x);
    if (lane == 0) wred[warp] = s;
    __syncthreads();
    if (warp == 0) {
        float v = (lane < 8) ? wred[lane] : 0.f;
        #pragma unroll
        for (int o = 4; o > 0; o >>= 1) v += __shfl_down_sync(0xFFFFFFFFu, v, o);
        if (lane == 0) wred[0] = v;
    }
    __syncthreads();
    const float m = wred[0] / (float)P;

    const bool  fg = own && (x > m);
    const float v  = fg ? (x - m + 1e-9f) : 0.f;

    lab[t]  = BIGL;                         // whole padded grid incl. border
    psum[t] = 0.f;
    __syncthreads();
    if (fg) lab[idx] = idx;                 // label = own padded index
    __syncthreads();

    // ---- 8-connected CC: min-propagation + double pointer jumping ----
    // label ordering (padded row-major) is lexicographic in (r,c), so the
    // component min is the same root pixel as flat row-major ordering.
    for (int it = 0; it < 64; ++it) {
        int wrote = 0;
        if (fg) {
            int l = lab[idx];
            int n;
            n = lab[idx - 17]; if (n < l) l = n;
            n = lab[idx - 16]; if (n < l) l = n;
            n = lab[idx - 15]; if (n < l) l = n;
            n = lab[idx -  1]; if (n < l) l = n;
            n = lab[idx +  1]; if (n < l) l = n;
            n = lab[idx + 15]; if (n < l) l = n;
            n = lab[idx + 16]; if (n < l) l = n;
            n = lab[idx + 17]; if (n < l) l = n;
            int j = lab[l]; if (j < l) l = j;   // pointer jump 1 (l is fg index)
            j     = lab[l]; if (j < l) l = j;   // pointer jump 2
            if (l < lab[idx]) { lab[idx] = l; wrote = 1; }
        }
        if (!__syncthreads_or(wrote)) break;    // barrier makes writes visible
    }

    // ---- B = sum of xv over mask ----
    float sb = warp_sum(v);
    if (lane == 0) wred[warp] = sb;
    __syncthreads();
    float B;
    if (warp == 0) {
        float bv = (lane < 8) ? wred[lane] : 0.f;
        #pragma unroll
        for (int o = 4; o > 0; o >>= 1) bv += __shfl_down_sync(0xFFFFFFFFu, bv, o);
        if (lane == 0) wred[0] = bv;
    }
    __syncthreads();
    B = wred[0];

    // ---- per-component sums ----
    if (fg) atomicAdd(&psum[lab[idx]], v);
    __syncthreads();

    // ---- entropy at component roots ----
    float h = 0.f;
    if (fg && lab[idx] == idx) {
        const float p = psum[idx] / B;      // in (0,1]
        h = -p * logf(p);
    }
    float sh = warp_sum(h);
    if (lane == 0) wred[warp] = sh;
    __syncthreads();
    if (warp == 0) {
        float hv = (lane < 8) ? wred[lane] : 0.f;
        #pragma unroll
        for (int o = 4; o > 0; o >>= 1) hv += __shfl_down_sync(0xFFFFFFFFu, hv, o);
        if (lane == 0) {
            g_partial[bh] = hv;
            __threadfence();
            unsigned int old = atomicAdd(&g_count, 1u);
            amLast = (old == NBH - 1);
        }
    }
    __syncthreads();

    // ---- last-arriving CTA does the deterministic final reduction ----
    if (amLast) {
        float acc = 0.f;
        #pragma unroll
        for (int i = t; i < NBH; i += 256) acc += g_partial[i];
        float sa = warp_sum(acc);
        if (lane == 0) wred[warp] = sa;
        __syncthreads();
        if (warp == 0) {
            float fv = (lane < 8) ? wred[lane] : 0.f;
            #pragma unroll
            for (int o = 4; o > 0; o >>= 1) fv += __shfl_down_sync(0xFFFFFFFFu, fv, o);
            if (lane == 0) {
                out[0]  = fv / (float)NBH;
                g_count = 0u;               // reset for next graph replay
            }
        }
    }
}

extern "C" void kernel_launch(void* const* d_in, const int* in_sizes, int n_in,
                              void* d_out, int out_size) {
    const float* in  = (const float*)d_in[0];
    float*       out = (float*)d_out;
    blob_kernel<<<NBH, 256>>>(in, out);
}

// round 3
// speedup vs baseline: 2.4200x; 2.1575x over previous
#include <cuda_runtime.h>

#define NBH        1536         // 128 batches * 12 heads
#define ROW        38809        // 197*197 elements per (b,h) slice
#define NW_PER_CTA 4
#define NCTA       (NBH / NW_PER_CTA)   // 384
#define FULL       0xFFFFFFFFu

__device__ float        g_partial[NCTA];
__device__ unsigned int g_count = 0;

__device__ __forceinline__ float bfly_sum(float v) {
    #pragma unroll
    for (int o = 16; o > 0; o >>= 1) v += __shfl_xor_sync(FULL, v, o);
    return v;
}

__global__ void __launch_bounds__(128)
blob_kernel(const float* __restrict__ in, float* __restrict__ out) {
    const int warp = threadIdx.x >> 5, lane = threadIdx.x & 31;
    const int bh   = blockIdx.x * NW_PER_CTA + warp;
    const size_t base = (size_t)bh * ROW + 1;

    // ---- load: lanes 0..13 -> row r cols 0..6 ; lanes 14..27 -> row (l-14) cols 7..13
    const int  r  = (lane < 14) ? lane : lane - 14;
    const int  cb = (lane < 14) ? 0 : 7;
    const bool ld = lane < 28;
    float xl[7];
    #pragma unroll
    for (int k = 0; k < 7; k++)
        xl[k] = ld ? in[base + r * 14 + cb + k] : 0.f;

    // lanes 0..13 assemble their full row of 14 via shuffle from lane+14
    float rowx[14];
    #pragma unroll
    for (int k = 0; k < 7; k++) {
        rowx[k]     = xl[k];
        rowx[7 + k] = __shfl_down_sync(FULL, xl[k], 14);
    }
    const bool isrow = lane < 14;

    // ---- mean over 196 ----
    float s = 0.f;
    if (isrow) {
        #pragma unroll
        for (int c = 0; c < 14; c++) s += rowx[c];
    }
    const float m = bfly_sum(s) * (1.f / 196.f);

    // ---- mask bits, xv values, B ----
    unsigned mask = 0u;
    float vs[14];
    float brow = 0.f;
    #pragma unroll
    for (int c = 0; c < 14; c++) {
        const bool fg = isrow && (rowx[c] > m);
        const float vv = fg ? (rowx[c] - m + 1e-9f) : 0.f;
        vs[c] = vv;
        brow += vv;
        if (fg) mask |= (1u << c);
    }
    const float B = bfly_sum(brow);
    const float invB = 1.f / B;         // B > 0 always (some x > mean)

    // ---- connected components via bit-parallel flood fill ----
    unsigned visited = 0u;
    float h = 0.f;
    for (int guard = 0; guard < 196; ++guard) {
        const unsigned rem = mask & ~visited;
        const unsigned bal = __ballot_sync(FULL, rem != 0u);
        if (!bal) break;
        const int      sl   = __ffs(bal) - 1;                 // seed lane (row)
        const unsigned remS = __shfl_sync(FULL, rem, sl);
        const unsigned seed = remS & (unsigned)(-(int)remS);  // lowest set bit
        unsigned comp = (lane == sl) ? seed : 0u;

        // flood to fixpoint: grow within row, OR grown neighbors rows, clip to mask
        for (int it = 0; it < 196; ++it) {
            const unsigned g  = comp | (comp << 1) | (comp >> 1);
            const unsigned gu = __shfl_up_sync(FULL, g, 1);   // row-1 (lane0: self, harmless)
            const unsigned gd = __shfl_down_sync(FULL, g, 1); // row+1 (lane13 pulls 0)
            const unsigned nc = mask & (g | gu | gd);
            const bool     done = !__any_sync(FULL, nc != comp);
            comp = nc;
            if (done) break;
        }
        visited |= comp;

        // component sum of xv (registers only), then entropy term
        float cs = 0.f;
        #pragma unroll
        for (int c = 0; c < 14; c++)
            if (comp & (1u << c)) cs += vs[c];
        const float pu = bfly_sum(cs);
        const float p  = pu * invB;     // in (0, 1]
        h += -p * logf(p);              // identical on all lanes
    }

    // ---- CTA combine + fused last-CTA global reduction ----
    __shared__ float wres[NW_PER_CTA];
    __shared__ float w2[NW_PER_CTA];
    __shared__ bool  amLast;
    if (lane == 0) wres[warp] = h;
    __syncthreads();
    if (threadIdx.x == 0) {
        float acc = 0.f;
        #pragma unroll
        for (int i = 0; i < NW_PER_CTA; i++) acc += wres[i];
        g_partial[blockIdx.x] = acc;
        __threadfence();
        amLast = (atomicAdd(&g_count, 1u) == NCTA - 1);
    }
    __syncthreads();

    if (amLast) {
        __threadfence();                // all partials visible (post-atomic)
        float acc = 0.f;
        for (int i = threadIdx.x; i < NCTA; i += 128) acc += g_partial[i];
        acc = bfly_sum(acc);
        if (lane == 0) w2[warp] = acc;
        __syncthreads();
        if (threadIdx.x == 0) {
            out[0]  = (w2[0] + w2[1] + w2[2] + w2[3]) * (1.f / (float)NBH);
            g_count = 0u;               // reset for next graph replay
        }
    }
}

extern "C" void kernel_launch(void* const* d_in, const int* in_sizes, int n_in,
                              void* d_out, int out_size) {
    const float* in  = (const float*)d_in[0];
    float*       out = (float*)d_out;
    blob_kernel<<<NCTA, 128>>>(in, out);
}